// round 15
// baseline (speedup 1.0000x reference)
#include <cuda_runtime.h>
#include <cuda_fp16.h>
#include <cstdint>
#include <math.h>

// Problem shape (fixed): B=8, T=2048, C=1024
constexpr int kB = 8;
constexpr int kT = 2048;
constexpr int kC = 1024;
constexpr int kM = kB * kT;                 // 16384 rows
constexpr size_t kMC = (size_t)kM * kC;
constexpr size_t kCC = (size_t)kC * kC;

constexpr int kSeg    = 32;                 // segments per sequence
constexpr int kSegLen = kT / kSeg;          // 64

// ---------------------------------------------------------------------------
// Scratch (__device__ globals)
// ---------------------------------------------------------------------------
__device__ __half g_a[3][kMC];     // mixed inputs (k,v,r) in fp16
__device__ __half g_w[4][kCC];     // wk,wv,wr,wo in fp16
__device__ __half g_k16[kMC];      // key (fp16)
__device__ __half g_v16[kMC];      // value (fp16)
__device__ __half g_r16[kMC];      // sigmoid(receptance) (fp16)
__device__ __half g_rw[kMC];       // rwkv in fp16
__device__ float g_segN[(size_t)kB * kSeg * kC];
__device__ float g_segD[(size_t)kB * kSeg * kC];
__device__ float g_segM[(size_t)kB * kSeg * kC];

// ---------------------------------------------------------------------------
// PTX helpers
// ---------------------------------------------------------------------------
__device__ __forceinline__ uint32_t smem_u32(const void* p) {
    uint32_t a;
    asm("{ .reg .u64 t; cvta.to.shared.u64 t, %1; cvt.u32.u64 %0, t; }"
        : "=r"(a) : "l"(p));
    return a;
}
__device__ __forceinline__ void cp_async16(uint32_t saddr, const void* gptr) {
    asm volatile("cp.async.ca.shared.global [%0], [%1], 16;"
                 :: "r"(saddr), "l"(gptr));
}
__device__ __forceinline__ void cp_commit() {
    asm volatile("cp.async.commit_group;");
}
template <int N>
__device__ __forceinline__ void cp_wait() {
    asm volatile("cp.async.wait_group %0;" :: "n"(N));
}
__device__ __forceinline__ void ldsm_x4(uint32_t* r, uint32_t addr) {
    asm volatile("ldmatrix.sync.aligned.m8n8.x4.shared.b16 {%0,%1,%2,%3}, [%4];"
                 : "=r"(r[0]), "=r"(r[1]), "=r"(r[2]), "=r"(r[3]) : "r"(addr));
}
__device__ __forceinline__ void mma16816(float* d, const uint32_t* a, const uint32_t* b) {
    asm volatile("mma.sync.aligned.m16n8k16.row.col.f32.f16.f16.f32 "
                 "{%0,%1,%2,%3}, {%4,%5,%6,%7}, {%8,%9}, {%0,%1,%2,%3};"
                 : "+f"(d[0]), "+f"(d[1]), "+f"(d[2]), "+f"(d[3])
                 : "r"(a[0]), "r"(a[1]), "r"(a[2]), "r"(a[3]), "r"(b[0]), "r"(b[1]));
}

__device__ __forceinline__ void h4_store(const float* a, __half* d, size_t off) {
    unsigned short u[4];
#pragma unroll
    for (int i = 0; i < 4; i++) u[i] = __half_as_ushort(__float2half_rn(a[i]));
    *(uint2*)(d + off) = make_uint2((uint32_t)u[0] | ((uint32_t)u[1] << 16),
                                    (uint32_t)u[2] | ((uint32_t)u[3] << 16));
}

// ---------------------------------------------------------------------------
// prep: weights + mixed inputs in ONE launch
// ---------------------------------------------------------------------------
__global__ __launch_bounds__(256) void prep_all_kernel(
    const float* __restrict__ x,
    const float* __restrict__ wk, const float* __restrict__ wv,
    const float* __restrict__ wr, const float* __restrict__ wo,
    const float* __restrict__ mk, const float* __restrict__ mv,
    const float* __restrict__ mr)
{
    const int bid = blockIdx.x;
    const int c4  = threadIdx.x;
    if (bid < 4096) {
        const int mat = bid >> 10;
        const int row = bid & 1023;
        const float* src = mat == 0 ? wk : mat == 1 ? wv : mat == 2 ? wr : wo;
        float4 v = ((const float4*)(src + (size_t)row * kC))[c4];
        h4_store((const float*)&v, g_w[mat], (size_t)row * kC + c4 * 4);
        return;
    }
    const int row = bid - 4096;
    const float4 xv = ((const float4*)(x + (size_t)row * kC))[c4];
    float4 pv = make_float4(0.f, 0.f, 0.f, 0.f);
    if ((row & (kT - 1)) != 0)
        pv = ((const float4*)(x + (size_t)(row - 1) * kC))[c4];
    const float4 m0 = ((const float4*)mk)[c4];
    const float4 m1 = ((const float4*)mv)[c4];
    const float4 m2 = ((const float4*)mr)[c4];
    const float* xe = (const float*)&xv;
    const float* pe = (const float*)&pv;
    const float* me[3] = {(const float*)&m0, (const float*)&m1, (const float*)&m2};
    const size_t off = (size_t)row * kC + c4 * 4;
#pragma unroll
    for (int s = 0; s < 3; s++) {
        float a[4];
#pragma unroll
        for (int i = 0; i < 4; i++)
            a[i] = fmaf(me[s][i], xe[i] - pe[i], pe[i]);
        h4_store(a, g_a[s], off);
    }
}

// ---------------------------------------------------------------------------
// fp16 warp-MMA GEMM: CTA 128x128, 4 warps, warp tile 64x64, K-chunk 64
// ---------------------------------------------------------------------------
constexpr int kStrideB16 = 72;
constexpr int kRowBytes  = kStrideB16 * 2;   // 144
constexpr int kTileBytes = 128 * kRowBytes;  // 18432
constexpr int kStageBytes = 2 * kTileBytes;  // 36864
constexpr int kSmemBytes  = 2 * kStageBytes; // 73728
constexpr int OFF_A = 0;
constexpr int OFF_B = kTileBytes;

__device__ __forceinline__ void load_chunk(uint32_t sb, int stage, int tid,
                                           const __half* A, const __half* B,
                                           int m0, int n0, int k0) {
    const uint32_t st = sb + stage * kStageBytes;
    const __half* srcs[2] = {A, B};
    const int bases[2] = {m0, n0};
    const uint32_t offs[2] = {OFF_A, OFF_B};
#pragma unroll
    for (int t = 0; t < 2; t++) {
#pragma unroll
        for (int rep = 0; rep < 8; rep++) {
            const int j = tid + rep * 128;
            const int row = j >> 3;
            const int seg = j & 7;
            const __half* g = srcs[t] + (size_t)(bases[t] + row) * kC + k0 + seg * 8;
            cp_async16(st + offs[t] + row * kRowBytes + seg * 16, g);
        }
    }
}

template <typename OutT, bool SIG>
__device__ __forceinline__ void gemm_body(const __half* __restrict__ A,
                                          const __half* __restrict__ B,
                                          OutT* __restrict__ out,
                                          int m0, int n0) {
    extern __shared__ char smem[];
    const uint32_t sb = smem_u32(smem);
    const int tid  = threadIdx.x;
    const int wid  = tid >> 5;
    const int lane = tid & 31;
    const int wm   = wid & 1;
    const int wn   = wid >> 1;

    float acc[4][8][4];
#pragma unroll
    for (int mt = 0; mt < 4; mt++)
#pragma unroll
        for (int nt = 0; nt < 8; nt++)
#pragma unroll
            for (int i = 0; i < 4; i++) acc[mt][nt][i] = 0.f;

    const uint32_t aRowOff = (uint32_t)((wm * 64 + (lane & 15)) * kRowBytes + (lane >> 4) * 16);
    const uint32_t bRowOff = (uint32_t)((wn * 64 + (lane & 7) + ((lane & 16) >> 1)) * kRowBytes
                                        + ((lane >> 3) & 1) * 16);

    load_chunk(sb, 0, tid, A, B, m0, n0, 0);
    cp_commit();

    const int nChunks = kC / 64;   // 16
    for (int c = 0; c < nChunks; c++) {
        if (c + 1 < nChunks) {
            load_chunk(sb, (c + 1) & 1, tid, A, B, m0, n0, (c + 1) * 64);
            cp_commit();
            cp_wait<1>();
        } else {
            cp_wait<0>();
        }
        __syncthreads();

        const uint32_t st = sb + (c & 1) * kStageBytes;
#pragma unroll
        for (int kk = 0; kk < 4; kk++) {
            const uint32_t kOff = kk * 32;
            uint32_t ah[4][4], b[8][2];
#pragma unroll
            for (int mt = 0; mt < 4; mt++)
                ldsm_x4(ah[mt], st + OFF_A + aRowOff + mt * 16 * kRowBytes + kOff);
#pragma unroll
            for (int np = 0; np < 4; np++)
                ldsm_x4(&b[np * 2][0], st + OFF_B + bRowOff + np * 16 * kRowBytes + kOff);
#pragma unroll
            for (int mt = 0; mt < 4; mt++)
#pragma unroll
                for (int nt = 0; nt < 8; nt++)
                    mma16816(acc[mt][nt], ah[mt], b[nt]);
        }
        __syncthreads();
    }

    const int mBase = m0 + wm * 64;
    const int nBase = n0 + wn * 64;
#pragma unroll
    for (int mt = 0; mt < 4; mt++) {
#pragma unroll
        for (int nt = 0; nt < 8; nt++) {
            float* a4 = acc[mt][nt];
            if (SIG) {
#pragma unroll
                for (int i = 0; i < 4; i++)
                    a4[i] = 1.f / (1.f + __expf(-a4[i]));
            }
            const int r0 = mBase + mt * 16 + (lane >> 2);
            const int cc = nBase + nt * 8 + (lane & 3) * 2;
            if constexpr (sizeof(OutT) == 4) {
                *(float2*)((float*)out + (size_t)r0 * kC + cc)       = make_float2(a4[0], a4[1]);
                *(float2*)((float*)out + (size_t)(r0 + 8) * kC + cc) = make_float2(a4[2], a4[3]);
            } else {
                *(__half2*)((__half*)out + (size_t)r0 * kC + cc)       = __floats2half2_rn(a4[0], a4[1]);
                *(__half2*)((__half*)out + (size_t)(r0 + 8) * kC + cc) = __floats2half2_rn(a4[2], a4[3]);
            }
        }
    }
}

// k and v GEMMs
__global__ __launch_bounds__(128, 2) void gemm_kv_kernel() {
    const int m0 = blockIdx.y * 128, n0 = blockIdx.x * 128;
    if (blockIdx.z == 0) gemm_body<__half, false>(g_a[0], g_w[0], g_k16, m0, n0);
    else                 gemm_body<__half, false>(g_a[1], g_w[1], g_v16, m0, n0);
}

// ---------------------------------------------------------------------------
// segA body (128-thread blocks), one-exp formulation, 8-step batched loads
// ---------------------------------------------------------------------------
__device__ void segA_body(int local, const float* __restrict__ td) {
    const int tid  = threadIdx.x;
    const int cblk = local & 7;                // 8 c-blocks of 128
    const int bs   = local >> 3;               // 0..255  (b*kSeg + seg)
    const int c = cblk * 128 + tid;
    const int b  = bs >> 5;
    const int sg = bs & (kSeg - 1);

    const float w = -__expf(td[c]);
    const size_t base = ((size_t)b * kT + (size_t)sg * kSegLen) * kC + c;
    const __half* kp = g_k16 + base;
    const __half* vp = g_v16 + base;

    float num = 0.f, den = 0.f, mx = -1e38f;
    for (int g = 0; g < kSegLen / 8; g++) {
        float kk[8], vv[8];
#pragma unroll
        for (int j = 0; j < 8; j++) {
            const size_t o = (size_t)(g * 8 + j) * kC;
            kk[j] = __half2float(kp[o]);
            vv[j] = __half2float(vp[o]);
        }
#pragma unroll
        for (int j = 0; j < 8; j++) {
            const float mw = mx + w;
            const float d  = mw - kk[j];
            const bool  p  = d >= 0.f;
            const float e  = __expf(p ? -d : d);
            const float f1 = p ? 1.f : e;
            const float f2 = p ? e : 1.f;
            num = fmaf(f1, num, f2 * vv[j]);
            den = fmaf(f1, den, f2);
            mx  = p ? mw : kk[j];
        }
    }
    const size_t si = (size_t)bs * kC + c;
    g_segN[si] = num;
    g_segD[si] = den;
    g_segM[si] = mx;
}

// combo: [0,1024) r-GEMM tiles; [1024, 3072) segA blocks. No cross deps.
__global__ __launch_bounds__(128, 2) void gemm_r_segA_kernel(const float* __restrict__ td) {
    const int bid = blockIdx.x;
    if (bid < 1024) {
        gemm_body<__half, true>(g_a[2], g_w[2], g_r16, (bid >> 3) * 128, (bid & 7) * 128);
    } else {
        segA_body(bid - 1024, td);
    }
}

// prefix over 32 segments, processed in 4 groups of 8 (MLP=24, low regs)
__global__ void wkv_prefix(const float* __restrict__ td) {
    const int idx = blockIdx.x * blockDim.x + threadIdx.x;
    const int b = idx >> 10;
    const int c = idx & (kC - 1);
    const float w = -__expf(td[c]);
    const float shift = (float)kSegLen * w;

    float N = 0.f, D = 0.f, M = -1e38f;
    for (int g = 0; g < kSeg / 8; g++) {
        float n[8], d[8], m[8];
#pragma unroll
        for (int j = 0; j < 8; j++) {
            const size_t si = ((size_t)(b * kSeg + g * 8 + j)) * kC + c;
            n[j] = g_segN[si];
            d[j] = g_segD[si];
            m[j] = g_segM[si];
        }
#pragma unroll
        for (int j = 0; j < 8; j++) {
            const size_t si = ((size_t)(b * kSeg + g * 8 + j)) * kC + c;
            g_segN[si] = N;
            g_segD[si] = D;
            g_segM[si] = M;
            const float Ms = M + shift;
            const float dd = Ms - m[j];
            const bool  p  = dd >= 0.f;
            const float e  = __expf(p ? -dd : dd);
            const float f1 = p ? 1.f : e;
            const float f2 = p ? e : 1.f;
            N = fmaf(f1, N, f2 * n[j]);
            D = fmaf(f1, D, f2 * d[j]);
            M = p ? Ms : m[j];
        }
    }
}

__global__ void wkv_segB(const float* __restrict__ td, const float* __restrict__ tf) {
    const int c  = blockIdx.x * blockDim.x + threadIdx.x;
    const int bs = blockIdx.y;                 // 0..255
    const int b  = bs >> 5;
    const int sg = bs & (kSeg - 1);

    const float w = -__expf(td[c]);
    const float u = tf[c];

    const size_t si = (size_t)bs * kC + c;
    float num = g_segN[si];
    float den = g_segD[si];
    float mx  = g_segM[si];

    const size_t base = ((size_t)b * kT + (size_t)sg * kSegLen) * kC + c;
    const __half* kp = g_k16 + base;
    const __half* vp = g_v16 + base;
    const __half* rp = g_r16 + base;
    __half* op = g_rw + base;

    for (int g = 0; g < kSegLen / 8; g++) {
        float kk[8], vv[8], rr[8];
#pragma unroll
        for (int j = 0; j < 8; j++) {
            const size_t o = (size_t)(g * 8 + j) * kC;
            kk[j] = __half2float(kp[o]);
            vv[j] = __half2float(vp[o]);
            rr[j] = __half2float(rp[o]);
        }
        __half ov[8];
#pragma unroll
        for (int j = 0; j < 8; j++) {
            const float ku  = kk[j] + u;
            const float do_ = mx - ku;
            const bool  po  = do_ >= 0.f;
            const float eo  = __expf(po ? -do_ : do_);
            const float g1  = po ? 1.f : eo;
            const float g2  = po ? eo : 1.f;
            const float outv = __fdividef(fmaf(g1, num, g2 * vv[j]), fmaf(g1, den, g2));
            const float mw = mx + w;
            const float d  = mw - kk[j];
            const bool  p  = d >= 0.f;
            const float e  = __expf(p ? -d : d);
            const float f1 = p ? 1.f : e;
            const float f2 = p ? e : 1.f;
            num = fmaf(f1, num, f2 * vv[j]);
            den = fmaf(f1, den, f2);
            mx  = p ? mw : kk[j];
            ov[j] = __float2half_rn(rr[j] * outv);
        }
#pragma unroll
        for (int j = 0; j < 8; j++)
            op[(size_t)(g * 8 + j) * kC] = ov[j];
    }
}

__global__ __launch_bounds__(128, 2) void gemm_out_kernel(float* __restrict__ out) {
    gemm_body<float, false>(g_rw, g_w[3], out, blockIdx.y * 128, blockIdx.x * 128);
}

// ---------------------------------------------------------------------------
// Launch
// ---------------------------------------------------------------------------
extern "C" void kernel_launch(void* const* d_in, const int* in_sizes, int n_in,
                              void* d_out, int out_size) {
    const float* x  = (const float*)d_in[0];
    const float* wk = (const float*)d_in[1];
    const float* wv = (const float*)d_in[2];
    const float* wr = (const float*)d_in[3];
    const float* wo = (const float*)d_in[4];
    const float* td = (const float*)d_in[5];
    const float* tf = (const float*)d_in[6];
    const float* mk = (const float*)d_in[7];
    const float* mv = (const float*)d_in[8];
    const float* mr = (const float*)d_in[9];
    float* out = (float*)d_out;

    cudaFuncSetAttribute(gemm_kv_kernel,     cudaFuncAttributeMaxDynamicSharedMemorySize, kSmemBytes);
    cudaFuncSetAttribute(gemm_r_segA_kernel, cudaFuncAttributeMaxDynamicSharedMemorySize, kSmemBytes);
    cudaFuncSetAttribute(gemm_out_kernel,    cudaFuncAttributeMaxDynamicSharedMemorySize, kSmemBytes);

    prep_all_kernel<<<4096 + kM, 256>>>(x, wk, wv, wr, wo, mk, mv, mr);
    gemm_kv_kernel<<<dim3(kC / 128, kM / 128, 2), 128, kSmemBytes>>>();
    gemm_r_segA_kernel<<<1024 + 2048, 128, kSmemBytes>>>(td);
    wkv_prefix<<<(kB * kC) / 256, 256>>>(td);
    wkv_segB<<<dim3(kC / 256, kB * kSeg), 256>>>(td, tf);
    gemm_out_kernel<<<dim3(kC / 128, kM / 128), 128, kSmemBytes>>>(out);
}